// round 2
// baseline (speedup 1.0000x reference)
#include <cuda_runtime.h>

// Transformed coefficient tensor in basis (1, cos x_i, sin x_i) per qubit,
// grouped for LDS.128: 9 groups (e0,e1) of 9 float2 entries (e2*3+e3),
// padded to 20 floats (= 5 x 16B) per group. 45 ulonglong2 = 720 B.
__device__ ulonglong2 g_C4[45];

// ---------------------------------------------------------------------------
// f32x2 packed helpers (ptxas will not auto-fuse; must come from PTX)
// ---------------------------------------------------------------------------
__device__ __forceinline__ unsigned long long pack2(float x, float y) {
    unsigned long long r;
    asm("mov.b64 %0, {%1, %2};" : "=l"(r) : "f"(x), "f"(y));
    return r;
}
__device__ __forceinline__ void unpack2(unsigned long long v, float& x, float& y) {
    asm("mov.b64 {%0, %1}, %2;" : "=f"(x), "=f"(y) : "l"(v));
}
__device__ __forceinline__ unsigned long long fma2(unsigned long long a,
                                                   unsigned long long b,
                                                   unsigned long long c) {
    unsigned long long d;
    asm("fma.rn.f32x2 %0, %1, %2, %3;" : "=l"(d) : "l"(a), "l"(b), "l"(c));
    return d;
}

// ---------------------------------------------------------------------------
// Precompute: build U (16x16 complex) from shared weights, fold head_w/head_b
// into two real symmetric quadratic forms, collapse onto the 81-coef tensor in
// the (c^2, cs, s^2) basis, then transform each axis to the (1, cos, sin)
// basis and store in the grouped/padded layout. One block, 256 threads.
// ---------------------------------------------------------------------------
__global__ void precompute_kernel(const float* __restrict__ w,
                                  const float* __restrict__ hw,
                                  const float* __restrict__ hb) {
    __shared__ float ur[16][16];
    __shared__ float ui[16][16];
    __shared__ float2 Ca[81];
    __shared__ float2 Cb[81];
    const int t = threadIdx.x;           // 0..255
    const int r = t >> 4, c = t & 15;

    ur[r][c] = (r == c) ? 1.0f : 0.0f;
    ui[r][c] = 0.0f;
    if (t < 81) Ca[t] = make_float2(0.0f, 0.0f);
    __syncthreads();

    for (int rep = 0; rep < 2; ++rep) {
        for (int i = 0; i < 4; ++i) {
            const int bidx = 3 - i;        // wire i <-> bit (3-i)
            const int bit  = 1 << bidx;
            // ---- RZ(weights[0,i,0])
            {
                const float th = w[i * 4 + 0];
                const float cz = cosf(0.5f * th);
                const float sz = sinf(0.5f * th);
                const float szz = (r & bit) ? sz : -sz;
                const float a = ur[r][c], b = ui[r][c];
                ur[r][c] = a * cz - b * szz;
                ui[r][c] = a * szz + b * cz;
            }
            __syncthreads();
            // ---- RY(weights[0,i,1])
            if (t < 128) {
                const float th = w[i * 4 + 1];
                const float cy = cosf(0.5f * th);
                const float sy = sinf(0.5f * th);
                const int cc = t & 15;
                const int rl = t >> 4;                 // 0..7
                const int lm = bit - 1;
                const int r0 = ((rl & ~lm) << 1) | (rl & lm);
                const int r1 = r0 | bit;
                const float a0r = ur[r0][cc], a0i = ui[r0][cc];
                const float a1r = ur[r1][cc], a1i = ui[r1][cc];
                ur[r0][cc] = cy * a0r - sy * a1r;
                ui[r0][cc] = cy * a0i - sy * a1i;
                ur[r1][cc] = sy * a0r + cy * a1r;
                ui[r1][cc] = sy * a0i + cy * a1i;
            }
            __syncthreads();
        }
        // ---- CNOT(wire0 -> wire1): swap rows r <-> r^4 for rows with bit8 set
        if (t < 64) {
            const int cc = t & 15;
            const int rl = t >> 4;           // 0..3
            const int ra = 8 + rl, rb = 12 + rl;
            float tr = ur[ra][cc]; ur[ra][cc] = ur[rb][cc]; ur[rb][cc] = tr;
            float ti = ui[ra][cc]; ui[ra][cc] = ui[rb][cc]; ui[rb][cc] = ti;
        }
        __syncthreads();
    }

    // H_j[k][m] = sum_row c_j[row] * Re(conj(U[row,k]) U[row,m]); bias on diag.
    {
        const int k = r, m = c;
        float h0 = 0.0f, h1 = 0.0f;
        const float hw00 = hw[0], hw01 = hw[1], hw02 = hw[2], hw03 = hw[3];
        const float hw10 = hw[4], hw11 = hw[5], hw12 = hw[6], hw13 = hw[7];
        #pragma unroll
        for (int row = 0; row < 16; ++row) {
            const float s0 = (row & 8) ? -1.0f : 1.0f;
            const float s1 = (row & 4) ? -1.0f : 1.0f;
            const float s2 = (row & 2) ? -1.0f : 1.0f;
            const float s3 = (row & 1) ? -1.0f : 1.0f;
            const float zc0 = hw00 * s0 + hw01 * s1 + hw02 * s2 + hw03 * s3;
            const float zc1 = hw10 * s0 + hw11 * s1 + hw12 * s2 + hw13 * s3;
            const float ov = ur[row][k] * ur[row][m] + ui[row][k] * ui[row][m];
            h0 += zc0 * ov;
            h1 += zc1 * ov;
        }
        if (k == m) { h0 += hb[0]; h1 += hb[1]; }

        // (k,m) -> base-3 index in (c^2, cs, s^2) basis: digit = k_i + m_i
        int g = 0;
        #pragma unroll
        for (int i = 0; i < 4; ++i) {
            const int sh = 3 - i;
            g = g * 3 + (((k >> sh) & 1) + ((m >> sh) & 1));
        }
        atomicAdd(&Ca[g].x, h0);
        atomicAdd(&Ca[g].y, h1);
    }

    // ---- Basis transform per axis: (c^2, cs, s^2) -> (1, cos, sin)
    //   c^2 = .5 + .5 cos ;  cs = .5 sin ;  s^2 = .5 - .5 cos
    //   => new[e=0] = .5*(old[0]+old[2]); new[e=1] = .5*(old[0]-old[2]);
    //      new[e=2] = .5*old[1]
    float2* src = Ca;
    float2* dst = Cb;
    const int strides[4] = {27, 9, 3, 1};
    for (int ax = 0; ax < 4; ++ax) {
        __syncthreads();
        if (t < 81) {
            const int st = strides[ax];
            const int pos = (t / st) % 3;
            const int base = t - pos * st;
            const float2 i0 = src[base];
            const float2 i1 = src[base + st];
            const float2 i2 = src[base + 2 * st];
            float2 o;
            if (pos == 0)      { o.x = 0.5f * (i0.x + i2.x); o.y = 0.5f * (i0.y + i2.y); }
            else if (pos == 1) { o.x = 0.5f * (i0.x - i2.x); o.y = 0.5f * (i0.y - i2.y); }
            else               { o.x = 0.5f * i1.x;          o.y = 0.5f * i1.y; }
            dst[t] = o;
        }
        float2* tmp = src; src = dst; dst = tmp;
    }
    __syncthreads();
    // After 4 passes the result sits back in Ca (== src).

    // ---- Store grouped/padded layout: group = e0*3+e1, entry k = e2*3+e3.
    float* gp = reinterpret_cast<float*>(g_C4);
    if (t < 81) {
        const int a  = t / 27;
        const int bq = (t / 9) % 3;
        const int k  = t % 9;
        const int off = (a * 3 + bq) * 20 + 2 * k;
        const float2 v = src[t];
        gp[off]     = v.x;
        gp[off + 1] = v.y;
    }
    if (t < 9) {               // zero the pads
        gp[t * 20 + 18] = 0.0f;
        gp[t * 20 + 19] = 0.0f;
    }
}

// ---------------------------------------------------------------------------
// Main kernel: per sample, 4x fast sincos(x) -> nested-Horner multilinear
// evaluation of the 81-coef tensor, both outputs packed in one f32x2 lane.
// 80 fma2 + 45 LDS.128 + 8 MUFU per sample.
// ---------------------------------------------------------------------------
__global__ void __launch_bounds__(256)
main_kernel(const float4* __restrict__ x4, float2* __restrict__ out, int B) {
    __shared__ ulonglong2 Cs[45];
    if (threadIdx.x < 45) Cs[threadIdx.x] = g_C4[threadIdx.x];
    __syncthreads();

    const int b = blockIdx.x * 256 + threadIdx.x;
    if (b >= B) return;

    const float4 xv = x4[b];
    float s0, c0, s1, c1, s2, c2, s3, c3;
    __sincosf(xv.x, &s0, &c0);
    __sincosf(xv.y, &s1, &c1);
    __sincosf(xv.z, &s2, &c2);
    __sincosf(xv.w, &s3, &c3);

    const unsigned long long pc0 = pack2(c0, c0), ps0 = pack2(s0, s0);
    const unsigned long long pc1 = pack2(c1, c1), ps1 = pack2(s1, s1);
    const unsigned long long pc2 = pack2(c2, c2), ps2 = pack2(s2, s2);
    const unsigned long long pc3 = pack2(c3, c3), ps3 = pack2(s3, s3);

    unsigned long long G[3];
    #pragma unroll
    for (int a = 0; a < 3; ++a) {
        unsigned long long E[3];
        #pragma unroll
        for (int bq = 0; bq < 3; ++bq) {
            const int g = a * 3 + bq;
            const ulonglong2 q0 = Cs[g * 5 + 0];
            const ulonglong2 q1 = Cs[g * 5 + 1];
            const ulonglong2 q2 = Cs[g * 5 + 2];
            const ulonglong2 q3 = Cs[g * 5 + 3];
            const ulonglong2 q4 = Cs[g * 5 + 4];
            // entries e0..e8 = (q0.x q0.y q1.x q1.y q2.x q2.y q3.x q3.y q4.x)
            unsigned long long t0 = fma2(pc3, q0.y, q0.x);
            t0 = fma2(ps3, q1.x, t0);
            unsigned long long t1 = fma2(pc3, q2.x, q1.y);
            t1 = fma2(ps3, q2.y, t1);
            unsigned long long t2 = fma2(pc3, q3.y, q3.x);
            t2 = fma2(ps3, q4.x, t2);
            E[bq] = fma2(ps2, t2, fma2(pc2, t1, t0));
        }
        G[a] = fma2(ps1, E[2], fma2(pc1, E[1], E[0]));
    }
    const unsigned long long F = fma2(ps0, G[2], fma2(pc0, G[1], G[0]));

    float o0, o1;
    unpack2(F, o0, o1);
    out[b] = make_float2(o0, o1);
}

extern "C" void kernel_launch(void* const* d_in, const int* in_sizes, int n_in,
                              void* d_out, int out_size) {
    const float* x  = (const float*)d_in[0];   // (B, 4) fp32
    const float* w  = (const float*)d_in[1];   // (2, 4, 4) fp32
    const float* hw = (const float*)d_in[2];   // (2, 4) fp32
    const float* hb = (const float*)d_in[3];   // (2,) fp32

    const int B = in_sizes[0] / 4;

    precompute_kernel<<<1, 256>>>(w, hw, hb);
    const int grid = (B + 255) / 256;
    main_kernel<<<grid, 256>>>((const float4*)x, (float2*)d_out, B);
}

// round 3
// speedup vs baseline: 1.0133x; 1.0133x over previous
#include <cuda_runtime.h>

// ---------------------------------------------------------------------------
// f32x2 packed helpers (ptxas never auto-fuses; must come from PTX)
// ---------------------------------------------------------------------------
__device__ __forceinline__ unsigned long long pack2(float x, float y) {
    unsigned long long r;
    asm("mov.b64 %0, {%1, %2};" : "=l"(r) : "f"(x), "f"(y));
    return r;
}
__device__ __forceinline__ unsigned long long fma2(unsigned long long a,
                                                   unsigned long long b,
                                                   unsigned long long c) {
    unsigned long long d;
    asm("fma.rn.f32x2 %0, %1, %2, %3;" : "=l"(d) : "l"(a), "l"(b), "l"(c));
    return d;
}

// ---------------------------------------------------------------------------
// Fused kernel. Per block:
//   Phase A (precompute, ~1.4K cyc): build U (16x16 complex) from the shared
//     weights, fold head_w/head_b into two real symmetric quadratic forms,
//     collapse onto an 81-coef tensor in the (c^2,cs,s^2) basis, transform to
//     the (1,cos,sin) basis, store grouped for LDS.128.
//   Phase B (samples): 4 samples/thread. Per sample: 4x fast sincos ->
//     nested-Horner multilinear evaluation, both outputs packed in one f32x2
//     lane. 80 fma2 + (45/4) LDS.128 per sample.
// ---------------------------------------------------------------------------
__global__ void __launch_bounds__(256, 2)
fused_kernel(const float4* __restrict__ x4,
             unsigned long long* __restrict__ out,
             const float* __restrict__ w,
             const float* __restrict__ hw,
             const float* __restrict__ hb,
             int B) {
    __shared__ float ur[16][16];
    __shared__ float ui[16][16];
    __shared__ float2 Ca[81];
    __shared__ float2 Cb[81];
    __shared__ ulonglong2 Cs[45];   // grouped/padded: 9 groups x 5 x 16B
    __shared__ float wcs[16];       // (cos,sin) of half-angles: [4i]=RZ c, [4i+1]=RZ s, [4i+2]=RY c, [4i+3]=RY s

    const int t = threadIdx.x;           // 0..255
    const int r = t >> 4, c = t & 15;

    // ---- issue x loads early; DRAM latency hides under precompute
    const int i0 = blockIdx.x * 1024 + t;
    const int i1 = i0 + 256, i2 = i0 + 512, i3 = i0 + 768;
    float4 xa = (i0 < B) ? x4[i0] : make_float4(0.f, 0.f, 0.f, 0.f);
    float4 xb = (i1 < B) ? x4[i1] : make_float4(0.f, 0.f, 0.f, 0.f);
    float4 xc = (i2 < B) ? x4[i2] : make_float4(0.f, 0.f, 0.f, 0.f);
    float4 xd = (i3 < B) ? x4[i3] : make_float4(0.f, 0.f, 0.f, 0.f);

    // ---- weight trig computed once (8 threads), not redundantly per thread
    if (t < 8) {
        const float th = w[(t >> 1) * 4 + (t & 1)];
        float s, co;
        sincosf(0.5f * th, &s, &co);
        wcs[2 * t] = co;
        wcs[2 * t + 1] = s;
    }
    ur[r][c] = (r == c) ? 1.0f : 0.0f;
    ui[r][c] = 0.0f;
    if (t < 81) Ca[t] = make_float2(0.0f, 0.0f);
    __syncthreads();

    // ================= Phase A: build U =================
    #pragma unroll 1
    for (int rep = 0; rep < 2; ++rep) {
        #pragma unroll 1
        for (int i = 0; i < 4; ++i) {
            const int bit = 1 << (3 - i);        // wire i <-> bit (3-i)
            // ---- RZ(weights[0,i,0])
            {
                const float cz = wcs[4 * i];
                const float sz = wcs[4 * i + 1];
                const float szz = (r & bit) ? sz : -sz;
                const float a = ur[r][c], b = ui[r][c];
                ur[r][c] = a * cz - b * szz;
                ui[r][c] = a * szz + b * cz;
            }
            __syncthreads();
            // ---- RY(weights[0,i,1])
            if (t < 128) {
                const float cy = wcs[4 * i + 2];
                const float sy = wcs[4 * i + 3];
                const int cc = t & 15;
                const int rl = t >> 4;                 // 0..7
                const int lm = bit - 1;
                const int r0 = ((rl & ~lm) << 1) | (rl & lm);
                const int r1 = r0 | bit;
                const float a0r = ur[r0][cc], a0i = ui[r0][cc];
                const float a1r = ur[r1][cc], a1i = ui[r1][cc];
                ur[r0][cc] = cy * a0r - sy * a1r;
                ui[r0][cc] = cy * a0i - sy * a1i;
                ur[r1][cc] = sy * a0r + cy * a1r;
                ui[r1][cc] = sy * a0i + cy * a1i;
            }
            __syncthreads();
        }
        // ---- CNOT(wire0 -> wire1): swap rows r <-> r^4 for rows with bit8
        if (t < 64) {
            const int cc = t & 15;
            const int rl = t >> 4;           // 0..3
            const int ra = 8 + rl, rb = 12 + rl;
            float tr = ur[ra][cc]; ur[ra][cc] = ur[rb][cc]; ur[rb][cc] = tr;
            float ti = ui[ra][cc]; ui[ra][cc] = ui[rb][cc]; ui[rb][cc] = ti;
        }
        __syncthreads();
    }

    // ---- quadratic forms: H_j[k][m] = sum_row c_j[row] Re(conj(U[row,k])U[row,m])
    {
        const int k = r, m = c;
        float h0 = 0.0f, h1 = 0.0f;
        const float hw00 = hw[0], hw01 = hw[1], hw02 = hw[2], hw03 = hw[3];
        const float hw10 = hw[4], hw11 = hw[5], hw12 = hw[6], hw13 = hw[7];
        #pragma unroll
        for (int row = 0; row < 16; ++row) {
            const float s0 = (row & 8) ? -1.0f : 1.0f;
            const float s1 = (row & 4) ? -1.0f : 1.0f;
            const float s2 = (row & 2) ? -1.0f : 1.0f;
            const float s3 = (row & 1) ? -1.0f : 1.0f;
            const float zc0 = hw00 * s0 + hw01 * s1 + hw02 * s2 + hw03 * s3;
            const float zc1 = hw10 * s0 + hw11 * s1 + hw12 * s2 + hw13 * s3;
            const float ov = ur[row][k] * ur[row][m] + ui[row][k] * ui[row][m];
            h0 += zc0 * ov;
            h1 += zc1 * ov;
        }
        if (k == m) { h0 += hb[0]; h1 += hb[1]; }   // bias folded into diagonal

        // (k,m) -> base-3 index in (c^2, cs, s^2) basis: digit = k_i + m_i
        int g = 0;
        #pragma unroll
        for (int i = 0; i < 4; ++i) {
            const int sh = 3 - i;
            g = g * 3 + (((k >> sh) & 1) + ((m >> sh) & 1));
        }
        atomicAdd(&Ca[g].x, h0);
        atomicAdd(&Ca[g].y, h1);
    }

    // ---- per-axis basis transform: (c^2, cs, s^2) -> (1, cos, sin)
    //   new[0] = .5*(old0+old2); new[1] = .5*(old0-old2); new[2] = .5*old1
    {
        float2* src = Ca;
        float2* dst = Cb;
        const int strides[4] = {27, 9, 3, 1};
        #pragma unroll 1
        for (int ax = 0; ax < 4; ++ax) {
            __syncthreads();
            if (t < 81) {
                const int st = strides[ax];
                const int pos = (t / st) % 3;
                const int base = t - pos * st;
                const float2 e0 = src[base];
                const float2 e1 = src[base + st];
                const float2 e2 = src[base + 2 * st];
                float2 o;
                if (pos == 0)      { o.x = 0.5f * (e0.x + e2.x); o.y = 0.5f * (e0.y + e2.y); }
                else if (pos == 1) { o.x = 0.5f * (e0.x - e2.x); o.y = 0.5f * (e0.y - e2.y); }
                else               { o.x = 0.5f * e1.x;          o.y = 0.5f * e1.y; }
                dst[t] = o;
            }
            float2* tmp = src; src = dst; dst = tmp;
        }
        __syncthreads();
        // 4 swaps -> result back in Ca (== src)

        // ---- grouped/padded layout: group g=(e0*3+e1), entries k=(e2*3+e3)
        float* gp = reinterpret_cast<float*>(Cs);
        if (t < 81) {
            const int a  = t / 27;
            const int bq = (t / 9) % 3;
            const int k  = t % 9;
            const float2 v = src[t];
            const int off = (a * 3 + bq) * 20 + 2 * k;
            gp[off]     = v.x;
            gp[off + 1] = v.y;
        }
        if (t < 9) {               // zero pads
            gp[t * 20 + 18] = 0.0f;
            gp[t * 20 + 19] = 0.0f;
        }
        __syncthreads();
    }

    // ================= Phase B: samples =================
    unsigned long long pc[4][4], ps[4][4];   // [sample][axis]
    {
        float sn, cn;
        #define DVQ_TRIG(S, XV)                                             \
            __sincosf((XV).x, &sn, &cn); pc[S][0] = pack2(cn, cn); ps[S][0] = pack2(sn, sn); \
            __sincosf((XV).y, &sn, &cn); pc[S][1] = pack2(cn, cn); ps[S][1] = pack2(sn, sn); \
            __sincosf((XV).z, &sn, &cn); pc[S][2] = pack2(cn, cn); ps[S][2] = pack2(sn, sn); \
            __sincosf((XV).w, &sn, &cn); pc[S][3] = pack2(cn, cn); ps[S][3] = pack2(sn, sn);
        DVQ_TRIG(0, xa)
        DVQ_TRIG(1, xb)
        DVQ_TRIG(2, xc)
        DVQ_TRIG(3, xd)
        #undef DVQ_TRIG
    }

    unsigned long long F[4], Gc[4];
    #pragma unroll
    for (int a = 0; a < 3; ++a) {
        #pragma unroll
        for (int bq = 0; bq < 3; ++bq) {
            const int g = a * 3 + bq;
            const ulonglong2 q0 = Cs[g * 5 + 0];
            const ulonglong2 q1 = Cs[g * 5 + 1];
            const ulonglong2 q2 = Cs[g * 5 + 2];
            const ulonglong2 q3 = Cs[g * 5 + 3];
            const ulonglong2 q4 = Cs[g * 5 + 4];
            #pragma unroll
            for (int s = 0; s < 4; ++s) {
                // entries e0..e8 = (q0.x q0.y q1.x q1.y q2.x q2.y q3.x q3.y q4.x)
                unsigned long long t0 = fma2(pc[s][3], q0.y, q0.x);
                t0 = fma2(ps[s][3], q1.x, t0);
                unsigned long long t1 = fma2(pc[s][3], q2.x, q1.y);
                t1 = fma2(ps[s][3], q2.y, t1);
                unsigned long long t2 = fma2(pc[s][3], q3.y, q3.x);
                t2 = fma2(ps[s][3], q4.x, t2);
                const unsigned long long E =
                    fma2(ps[s][2], t2, fma2(pc[s][2], t1, t0));
                if (bq == 0)      Gc[s] = E;
                else if (bq == 1) Gc[s] = fma2(pc[s][1], E, Gc[s]);
                else              Gc[s] = fma2(ps[s][1], E, Gc[s]);
            }
        }
        #pragma unroll
        for (int s = 0; s < 4; ++s) {
            if (a == 0)      F[s] = Gc[s];
            else if (a == 1) F[s] = fma2(pc[s][0], Gc[s], F[s]);
            else             F[s] = fma2(ps[s][0], Gc[s], F[s]);
        }
    }

    if (i0 < B) out[i0] = F[0];
    if (i1 < B) out[i1] = F[1];
    if (i2 < B) out[i2] = F[2];
    if (i3 < B) out[i3] = F[3];
}

extern "C" void kernel_launch(void* const* d_in, const int* in_sizes, int n_in,
                              void* d_out, int out_size) {
    const float* x  = (const float*)d_in[0];   // (B, 4) fp32
    const float* w  = (const float*)d_in[1];   // (2, 4, 4) fp32
    const float* hw = (const float*)d_in[2];   // (2, 4) fp32
    const float* hb = (const float*)d_in[3];   // (2,) fp32

    const int B = in_sizes[0] / 4;
    const int grid = (B + 1023) / 1024;        // 1024 samples per block

    fused_kernel<<<grid, 256>>>((const float4*)x,
                                (unsigned long long*)d_out,
                                w, hw, hb, B);
}

// round 5
// speedup vs baseline: 1.1555x; 1.1404x over previous
#include <cuda_runtime.h>

// Transformed coefficient tensor in basis (1, cos x_i, sin x_i) per qubit,
// grouped for LDS.128: 9 groups (e0,e1) of 9 float2 entries (e2*3+e3),
// padded to 20 floats (= 5 x 16B) per group. 45 ulonglong2 = 720 B.
__device__ ulonglong2 g_C4[45];

// ---------------------------------------------------------------------------
// f32x2 packed helpers (ptxas never auto-fuses; must come from PTX)
// ---------------------------------------------------------------------------
__device__ __forceinline__ unsigned long long pack2(float x, float y) {
    unsigned long long r;
    asm("mov.b64 %0, {%1, %2};" : "=l"(r) : "f"(x), "f"(y));
    return r;
}
__device__ __forceinline__ unsigned long long fma2(unsigned long long a,
                                                   unsigned long long b,
                                                   unsigned long long c) {
    unsigned long long d;
    asm("fma.rn.f32x2 %0, %1, %2, %3;" : "=l"(d) : "l"(a), "l"(b), "l"(c));
    return d;
}

// ---------------------------------------------------------------------------
// Precompute (1 block, 256 threads): build U (16x16 complex) from shared
// weights, fold head_w/head_b into two real symmetric quadratic forms,
// collapse onto the 81-coef tensor in the (c^2,cs,s^2) basis, transform each
// axis to the (1,cos,sin) basis, store grouped/padded. Hidden under the main
// kernel's trig prologue via PDL.
// ---------------------------------------------------------------------------
__global__ void precompute_kernel(const float* __restrict__ w,
                                  const float* __restrict__ hw,
                                  const float* __restrict__ hb) {
    __shared__ float ur[16][16];
    __shared__ float ui[16][16];
    __shared__ float2 Ca[81];
    __shared__ float2 Cb[81];
    const int t = threadIdx.x;           // 0..255
    const int r = t >> 4, c = t & 15;

    ur[r][c] = (r == c) ? 1.0f : 0.0f;
    ui[r][c] = 0.0f;
    if (t < 81) Ca[t] = make_float2(0.0f, 0.0f);
    __syncthreads();

    for (int rep = 0; rep < 2; ++rep) {
        for (int i = 0; i < 4; ++i) {
            const int bit = 1 << (3 - i);        // wire i <-> bit (3-i)
            // ---- RZ(weights[0,i,0])
            {
                const float th = w[i * 4 + 0];
                const float cz = cosf(0.5f * th);
                const float sz = sinf(0.5f * th);
                const float szz = (r & bit) ? sz : -sz;
                const float a = ur[r][c], b = ui[r][c];
                ur[r][c] = a * cz - b * szz;
                ui[r][c] = a * szz + b * cz;
            }
            __syncthreads();
            // ---- RY(weights[0,i,1])
            if (t < 128) {
                const float th = w[i * 4 + 1];
                const float cy = cosf(0.5f * th);
                const float sy = sinf(0.5f * th);
                const int cc = t & 15;
                const int rl = t >> 4;                 // 0..7
                const int lm = bit - 1;
                const int r0 = ((rl & ~lm) << 1) | (rl & lm);
                const int r1 = r0 | bit;
                const float a0r = ur[r0][cc], a0i = ui[r0][cc];
                const float a1r = ur[r1][cc], a1i = ui[r1][cc];
                ur[r0][cc] = cy * a0r - sy * a1r;
                ui[r0][cc] = cy * a0i - sy * a1i;
                ur[r1][cc] = sy * a0r + cy * a1r;
                ui[r1][cc] = sy * a0i + cy * a1i;
            }
            __syncthreads();
        }
        // ---- CNOT(wire0 -> wire1): swap rows r <-> r^4 for rows with bit8
        if (t < 64) {
            const int cc = t & 15;
            const int rl = t >> 4;           // 0..3
            const int ra = 8 + rl, rb = 12 + rl;
            float tr = ur[ra][cc]; ur[ra][cc] = ur[rb][cc]; ur[rb][cc] = tr;
            float ti = ui[ra][cc]; ui[ra][cc] = ui[rb][cc]; ui[rb][cc] = ti;
        }
        __syncthreads();
    }

    // H_j[k][m] = sum_row c_j[row] * Re(conj(U[row,k]) U[row,m]); bias on diag.
    {
        const int k = r, m = c;
        float h0 = 0.0f, h1 = 0.0f;
        const float hw00 = hw[0], hw01 = hw[1], hw02 = hw[2], hw03 = hw[3];
        const float hw10 = hw[4], hw11 = hw[5], hw12 = hw[6], hw13 = hw[7];
        #pragma unroll
        for (int row = 0; row < 16; ++row) {
            const float s0 = (row & 8) ? -1.0f : 1.0f;
            const float s1 = (row & 4) ? -1.0f : 1.0f;
            const float s2 = (row & 2) ? -1.0f : 1.0f;
            const float s3 = (row & 1) ? -1.0f : 1.0f;
            const float zc0 = hw00 * s0 + hw01 * s1 + hw02 * s2 + hw03 * s3;
            const float zc1 = hw10 * s0 + hw11 * s1 + hw12 * s2 + hw13 * s3;
            const float ov = ur[row][k] * ur[row][m] + ui[row][k] * ui[row][m];
            h0 += zc0 * ov;
            h1 += zc1 * ov;
        }
        if (k == m) { h0 += hb[0]; h1 += hb[1]; }

        // (k,m) -> base-3 index in (c^2, cs, s^2) basis: digit = k_i + m_i
        int g = 0;
        #pragma unroll
        for (int i = 0; i < 4; ++i) {
            const int sh = 3 - i;
            g = g * 3 + (((k >> sh) & 1) + ((m >> sh) & 1));
        }
        atomicAdd(&Ca[g].x, h0);
        atomicAdd(&Ca[g].y, h1);
    }

    // ---- per-axis basis transform: (c^2, cs, s^2) -> (1, cos, sin)
    //   new[0] = .5*(old0+old2); new[1] = .5*(old0-old2); new[2] = .5*old1
    float2* src = Ca;
    float2* dst = Cb;
    const int strides[4] = {27, 9, 3, 1};
    for (int ax = 0; ax < 4; ++ax) {
        __syncthreads();
        if (t < 81) {
            const int st = strides[ax];
            const int pos = (t / st) % 3;
            const int base = t - pos * st;
            const float2 e0 = src[base];
            const float2 e1 = src[base + st];
            const float2 e2 = src[base + 2 * st];
            float2 o;
            if (pos == 0)      { o.x = 0.5f * (e0.x + e2.x); o.y = 0.5f * (e0.y + e2.y); }
            else if (pos == 1) { o.x = 0.5f * (e0.x - e2.x); o.y = 0.5f * (e0.y - e2.y); }
            else               { o.x = 0.5f * e1.x;          o.y = 0.5f * e1.y; }
            dst[t] = o;
        }
        float2* tmp = src; src = dst; dst = tmp;
    }
    __syncthreads();
    // 4 swaps -> result back in Ca (== src)

    // ---- grouped/padded layout: group g=(e0*3+e1), entries k=(e2*3+e3)
    float* gp = reinterpret_cast<float*>(g_C4);
    if (t < 81) {
        const int a  = t / 27;
        const int bq = (t / 9) % 3;
        const int k  = t % 9;
        const float2 v = src[t];
        const int off = (a * 3 + bq) * 20 + 2 * k;
        gp[off]     = v.x;
        gp[off + 1] = v.y;
    }
    if (t < 9) {               // zero pads
        gp[t * 20 + 18] = 0.0f;
        gp[t * 20 + 19] = 0.0f;
    }
}

// ---------------------------------------------------------------------------
// Main kernel (PDL downstream): loads x and runs all trig BEFORE the grid
// dependency sync, so the upstream precompute is fully hidden. Then stages
// the 720 B table into smem and evaluates the multilinear form by nested
// Horner with f32x2 packed FMAs: 4 samples/thread, both outputs per lane.
// ---------------------------------------------------------------------------
__global__ void __launch_bounds__(256)
main_kernel(const float4* __restrict__ x4,
            unsigned long long* __restrict__ out,
            int B) {
    __shared__ ulonglong2 Cs[45];

    const int t = threadIdx.x;
    const int i0 = blockIdx.x * 1024 + t;
    const int i1 = i0 + 256, i2 = i0 + 512, i3 = i0 + 768;

    // ---- independent prologue: x loads + trig (upstream-agnostic)
    const float4 xa = (i0 < B) ? x4[i0] : make_float4(0.f, 0.f, 0.f, 0.f);
    const float4 xb = (i1 < B) ? x4[i1] : make_float4(0.f, 0.f, 0.f, 0.f);
    const float4 xc = (i2 < B) ? x4[i2] : make_float4(0.f, 0.f, 0.f, 0.f);
    const float4 xd = (i3 < B) ? x4[i3] : make_float4(0.f, 0.f, 0.f, 0.f);

    unsigned long long pc[4][4], ps[4][4];   // [sample][axis]
    {
        float sn, cn;
        #define DVQ_TRIG(S, XV)                                                              \
            __sincosf((XV).x, &sn, &cn); pc[S][0] = pack2(cn, cn); ps[S][0] = pack2(sn, sn); \
            __sincosf((XV).y, &sn, &cn); pc[S][1] = pack2(cn, cn); ps[S][1] = pack2(sn, sn); \
            __sincosf((XV).z, &sn, &cn); pc[S][2] = pack2(cn, cn); ps[S][2] = pack2(sn, sn); \
            __sincosf((XV).w, &sn, &cn); pc[S][3] = pack2(cn, cn); ps[S][3] = pack2(sn, sn);
        DVQ_TRIG(0, xa)
        DVQ_TRIG(1, xb)
        DVQ_TRIG(2, xc)
        DVQ_TRIG(3, xd)
        #undef DVQ_TRIG
    }

    // ---- wait for precompute results, then stage table into shared
    cudaGridDependencySynchronize();
    if (t < 45) Cs[t] = g_C4[t];
    __syncthreads();

    // ---- nested-Horner multilinear evaluation
    unsigned long long F[4], Gc[4];
    #pragma unroll
    for (int a = 0; a < 3; ++a) {
        #pragma unroll
        for (int bq = 0; bq < 3; ++bq) {
            const int g = a * 3 + bq;
            const ulonglong2 q0 = Cs[g * 5 + 0];
            const ulonglong2 q1 = Cs[g * 5 + 1];
            const ulonglong2 q2 = Cs[g * 5 + 2];
            const ulonglong2 q3 = Cs[g * 5 + 3];
            const ulonglong2 q4 = Cs[g * 5 + 4];
            #pragma unroll
            for (int s = 0; s < 4; ++s) {
                // entries e0..e8 = (q0.x q0.y q1.x q1.y q2.x q2.y q3.x q3.y q4.x)
                unsigned long long t0 = fma2(pc[s][3], q0.y, q0.x);
                t0 = fma2(ps[s][3], q1.x, t0);
                unsigned long long t1 = fma2(pc[s][3], q2.x, q1.y);
                t1 = fma2(ps[s][3], q2.y, t1);
                unsigned long long t2 = fma2(pc[s][3], q3.y, q3.x);
                t2 = fma2(ps[s][3], q4.x, t2);
                const unsigned long long E =
                    fma2(ps[s][2], t2, fma2(pc[s][2], t1, t0));
                if (bq == 0)      Gc[s] = E;
                else if (bq == 1) Gc[s] = fma2(pc[s][1], E, Gc[s]);
                else              Gc[s] = fma2(ps[s][1], E, Gc[s]);
            }
        }
        #pragma unroll
        for (int s = 0; s < 4; ++s) {
            if (a == 0)      F[s] = Gc[s];
            else if (a == 1) F[s] = fma2(pc[s][0], Gc[s], F[s]);
            else             F[s] = fma2(ps[s][0], Gc[s], F[s]);
        }
    }

    if (i0 < B) out[i0] = F[0];
    if (i1 < B) out[i1] = F[1];
    if (i2 < B) out[i2] = F[2];
    if (i3 < B) out[i3] = F[3];
}

extern "C" void kernel_launch(void* const* d_in, const int* in_sizes, int n_in,
                              void* d_out, int out_size) {
    const float* x  = (const float*)d_in[0];   // (B, 4) fp32
    const float* w  = (const float*)d_in[1];   // (2, 4, 4) fp32
    const float* hw = (const float*)d_in[2];   // (2, 4) fp32
    const float* hb = (const float*)d_in[3];   // (2,) fp32

    const int B = in_sizes[0] / 4;
    const int grid = (B + 1023) / 1024;        // 1024 samples per block

    // Upstream: table build (1 block).
    precompute_kernel<<<1, 256>>>(w, hw, hb);

    // Downstream: launched with programmatic stream serialization so its
    // prologue (x loads + trig) overlaps the precompute kernel; it gates on
    // cudaGridDependencySynchronize() before reading the table.
    cudaLaunchConfig_t cfg = {};
    cfg.gridDim  = dim3((unsigned)grid, 1, 1);
    cfg.blockDim = dim3(256, 1, 1);
    cfg.dynamicSmemBytes = 0;
    cfg.stream = 0;
    cudaLaunchAttribute attrs[1];
    attrs[0].id = cudaLaunchAttributeProgrammaticStreamSerialization;
    attrs[0].val.programmaticStreamSerializationAllowed = 1;
    cfg.attrs = attrs;
    cfg.numAttrs = 1;

    cudaLaunchKernelEx(&cfg, main_kernel,
                       (const float4*)x, (unsigned long long*)d_out, B);
}